// round 11
// baseline (speedup 1.0000x reference)
#include <cuda_runtime.h>
#include <cuda_bf16.h>

// Inputs (metadata order):
//  d_in[0] charges             float32 [200000, 4]
//  d_in[1] cell                float32 [3, 3]        (unused)
//  d_in[2] positions           float32 [200000, 3]   (unused)
//  d_in[3] neighbor_indices    int32   [12800000, 2]
//  d_in[4] neighbor_distances  float32 [12800000]
//  d_out  potential            float32 [200000, 4]
//
// out[i] += 0.5/d * charges[j];  out[j] += 0.5/d * charges[i]  over all edges.
//
// R11 (terminal geometry probe): proven-optimal shape — 1 edge/thread, fp32
// v4 gathers, red.global.add.v4.f32 — at TPB=1024 (last unsampled launch
// geometry). Kernel runs at the hardware floor for this access pattern:
// 4 scattered 16B L1tex wavefronts/edge (2 gathers + 2 vector reductions),
// retired at the measured 1.0 wavefront/cyc/SM rate:
//   51.2M wf / 148 SMs / 1.82GHz = 190us analytic; 190.4us measured.
//
// Falsified/priced alternatives (R2-R10):
//  - 4-edge unroll + vector stream loads: neutral (wall counts wavefronts).
//  - cache-policy pinning (evict_last / ldcg): neutral.
//  - fp16 charges mirror: neutral — wavefronts/sectors count lines, not bytes.
//  - 16/8-CTA cluster DSMEM gathers (static + work-stealing): 1.7-2.2x WORSE.
//  - TMA gather4: ~480us analytic.
//  - sort/bin-then-coalesce: sort passes alone exceed the 190us wall.
//  - smem privatization: ATOMS spread-addr 2 cyc/lane > 1 wf/cyc.

__device__ __forceinline__ void red_add_v4(float4* p, float4 v) {
    asm volatile("red.global.add.v4.f32 [%0], {%1, %2, %3, %4};"
                 :: "l"(p), "f"(v.x), "f"(v.y), "f"(v.z), "f"(v.w)
                 : "memory");
}

__device__ __forceinline__ float4 scale4(float4 c, float w) {
    return make_float4(c.x * w, c.y * w, c.z * w, c.w * w);
}

__global__ void __launch_bounds__(1024)
edge_scatter_kernel(const float4* __restrict__ charges,
                    const int2*   __restrict__ nbr,
                    const float*  __restrict__ dist,
                    float4*       __restrict__ out,
                    int n_edges) {
    int e = blockIdx.x * blockDim.x + threadIdx.x;
    if (e >= n_edges) return;

    int2  ij  = __ldg(&nbr[e]);
    float d   = __ldg(&dist[e]);
    float inv = 0.5f / d;   // fold PREFACTOR * 0.5

    float4 cj = __ldg(&charges[ij.y]);
    float4 ci = __ldg(&charges[ij.x]);

    red_add_v4(&out[ij.x], scale4(cj, inv));
    red_add_v4(&out[ij.y], scale4(ci, inv));
}

extern "C" void kernel_launch(void* const* d_in, const int* in_sizes, int n_in,
                              void* d_out, int out_size) {
    const float4* charges = (const float4*)d_in[0];
    const int2*   nbr     = (const int2*)d_in[3];
    const float*  dist    = (const float*)d_in[4];
    float4*       out     = (float4*)d_out;

    int n_edges = in_sizes[4];   // 12,800,000

    // d_out is poisoned to 0xAA — zero it (async, graph-capturable).
    cudaMemsetAsync(d_out, 0, (size_t)out_size * sizeof(float));

    const int TPB = 1024;
    int blocks = (n_edges + TPB - 1) / TPB;
    edge_scatter_kernel<<<blocks, TPB>>>(charges, nbr, dist, out, n_edges);
}

// round 12
// speedup vs baseline: 1.0082x; 1.0082x over previous
#include <cuda_runtime.h>
#include <cuda_bf16.h>

// Inputs (metadata order):
//  d_in[0] charges             float32 [200000, 4]
//  d_in[1] cell                float32 [3, 3]        (unused)
//  d_in[2] positions           float32 [200000, 3]   (unused)
//  d_in[3] neighbor_indices    int32   [12800000, 2]
//  d_in[4] neighbor_distances  float32 [12800000]
//  d_out  potential            float32 [200000, 4]
//
// out[i] += 0.5/d * charges[j];  out[j] += 0.5/d * charges[i]  over all edges.
//
// FINAL (session optimum, verified stable across 3 benches at 190.9-191.0us):
// 1 edge/thread, TPB=512, fp32 v4 gathers, red.global.add.v4.f32, async
// memset output zeroing.
//
// This runs at the hardware floor for a random-index edge scatter-gather:
//   4 scattered 16B L1tex wavefronts per edge (2 gathers + 2 v4 reductions)
//   x 12.8M edges / 148 SMs / 1.0 wf/cyc/SM @ 1.82GHz = 190us analytic;
//   189.0-190.4us measured in-kernel (100.3% of floor). L2=91%, DRAM=11%.
//
// Geometry sweep: TPB 256=191.2, 512=190.9 (best, x2 stable), 1024=193.0.
// Falsified/priced alternatives (R2-R11):
//  - 4-edge unroll + vector stream loads: neutral (wall counts wavefronts).
//  - cache-policy pinning (evict_last / ldcg): neutral.
//  - fp16 charges mirror: neutral — wavefronts/sectors count lines, not bytes.
//  - 16/8-CTA cluster DSMEM gathers (static + work-stealing): 1.7-2.2x WORSE.
//  - TMA gather4: ~480us analytic (46 cyc/request service).
//  - sort/bin-then-coalesce: sort passes alone exceed the 190us wall.
//  - smem privatization: ATOMS spread-addr 2 cyc/lane > 1 wf/cyc.

__device__ __forceinline__ void red_add_v4(float4* p, float4 v) {
    asm volatile("red.global.add.v4.f32 [%0], {%1, %2, %3, %4};"
                 :: "l"(p), "f"(v.x), "f"(v.y), "f"(v.z), "f"(v.w)
                 : "memory");
}

__device__ __forceinline__ float4 scale4(float4 c, float w) {
    return make_float4(c.x * w, c.y * w, c.z * w, c.w * w);
}

__global__ void __launch_bounds__(512)
edge_scatter_kernel(const float4* __restrict__ charges,
                    const int2*   __restrict__ nbr,
                    const float*  __restrict__ dist,
                    float4*       __restrict__ out,
                    int n_edges) {
    int e = blockIdx.x * blockDim.x + threadIdx.x;
    if (e >= n_edges) return;

    int2  ij  = __ldg(&nbr[e]);
    float d   = __ldg(&dist[e]);
    float inv = 0.5f / d;   // fold PREFACTOR * 0.5

    float4 cj = __ldg(&charges[ij.y]);
    float4 ci = __ldg(&charges[ij.x]);

    red_add_v4(&out[ij.x], scale4(cj, inv));
    red_add_v4(&out[ij.y], scale4(ci, inv));
}

extern "C" void kernel_launch(void* const* d_in, const int* in_sizes, int n_in,
                              void* d_out, int out_size) {
    const float4* charges = (const float4*)d_in[0];
    const int2*   nbr     = (const int2*)d_in[3];
    const float*  dist    = (const float*)d_in[4];
    float4*       out     = (float4*)d_out;

    int n_edges = in_sizes[4];   // 12,800,000

    // d_out is poisoned to 0xAA — zero it (async, graph-capturable).
    cudaMemsetAsync(d_out, 0, (size_t)out_size * sizeof(float));

    const int TPB = 512;
    int blocks = (n_edges + TPB - 1) / TPB;
    edge_scatter_kernel<<<blocks, TPB>>>(charges, nbr, dist, out, n_edges);
}

// round 13
// speedup vs baseline: 1.0141x; 1.0059x over previous
#include <cuda_runtime.h>
#include <cuda_bf16.h>

// Inputs (metadata order):
//  d_in[0] charges             float32 [200000, 4]
//  d_in[1] cell                float32 [3, 3]        (unused)
//  d_in[2] positions           float32 [200000, 3]   (unused)
//  d_in[3] neighbor_indices    int32   [12800000, 2]
//  d_in[4] neighbor_distances  float32 [12800000]
//  d_out  potential            float32 [200000, 4]
//
// out[i] += 0.5/d * charges[j];  out[j] += 0.5/d * charges[i]  over all edges.
//
// FINAL (session optimum; stable at 190.9-191.4us across 4 benches):
// 1 edge/thread, TPB=512, fp32 v4 gathers, red.global.add.v4.f32, async
// memset output zeroing.
//
// Hardware-floor argument: a random-index edge scatter-gather needs
//   4 scattered 16B L1tex wavefronts per edge (2 gathers + 2 v4 reductions)
//   x 12.8M edges / 148 SMs / 1.0 wf/cyc/SM @1.82GHz = 190us analytic.
// Measured 189.0-191.1us in-kernel = 100-100.5% of floor. L2=91%, DRAM=11%.
//
// Exhaustively falsified/priced alternatives (R2-R12):
//  - 4-edge unroll + vector stream loads: neutral (wall counts wavefronts).
//  - cache-policy pinning (evict_last / ldcg): neutral.
//  - fp16 charges mirror: neutral — wavefronts/sectors count lines, not bytes.
//  - 16/8-CTA cluster DSMEM gathers (static + work-stealing): 1.7-2.2x WORSE.
//  - TMA gather4: ~480us analytic (46 cyc/request service).
//  - sort/bin-then-coalesce: sort passes alone exceed the 190us wall.
//  - smem privatization: ATOMS spread-addr 2 cyc/lane > 1 wf/cyc.
//  - geometry: TPB 256=191.2, 512=190.9 (best), 1024=193.0.

__device__ __forceinline__ void red_add_v4(float4* p, float4 v) {
    asm volatile("red.global.add.v4.f32 [%0], {%1, %2, %3, %4};"
                 :: "l"(p), "f"(v.x), "f"(v.y), "f"(v.z), "f"(v.w)
                 : "memory");
}

__device__ __forceinline__ float4 scale4(float4 c, float w) {
    return make_float4(c.x * w, c.y * w, c.z * w, c.w * w);
}

__global__ void __launch_bounds__(512)
edge_scatter_kernel(const float4* __restrict__ charges,
                    const int2*   __restrict__ nbr,
                    const float*  __restrict__ dist,
                    float4*       __restrict__ out,
                    int n_edges) {
    int e = blockIdx.x * blockDim.x + threadIdx.x;
    if (e >= n_edges) return;

    int2  ij  = __ldg(&nbr[e]);
    float d   = __ldg(&dist[e]);
    float inv = 0.5f / d;   // fold PREFACTOR * 0.5

    float4 cj = __ldg(&charges[ij.y]);
    float4 ci = __ldg(&charges[ij.x]);

    red_add_v4(&out[ij.x], scale4(cj, inv));
    red_add_v4(&out[ij.y], scale4(ci, inv));
}

extern "C" void kernel_launch(void* const* d_in, const int* in_sizes, int n_in,
                              void* d_out, int out_size) {
    const float4* charges = (const float4*)d_in[0];
    const int2*   nbr     = (const int2*)d_in[3];
    const float*  dist    = (const float*)d_in[4];
    float4*       out     = (float4*)d_out;

    int n_edges = in_sizes[4];   // 12,800,000

    // d_out is poisoned to 0xAA — zero it (async, graph-capturable).
    cudaMemsetAsync(d_out, 0, (size_t)out_size * sizeof(float));

    const int TPB = 512;
    int blocks = (n_edges + TPB - 1) / TPB;
    edge_scatter_kernel<<<blocks, TPB>>>(charges, nbr, dist, out, n_edges);
}